// round 12
// baseline (speedup 1.0000x reference)
#include <cuda_runtime.h>
#include <cuda_fp16.h>
#include <cstdint>

#define BB 256
#define NN 128
#define CC 256

// B = W^T fp16 image, pre-swizzled quad-XOR: [8 chunks 16KB][256 rows 64B].
__device__ __align__(16) unsigned char g_Bh[131072];
// A fp16 images, same layout per batch: [8 chunks 8KB][128 rows 64B].
__device__ __align__(16) unsigned char g_Ah[(size_t)BB * 65536];

__device__ __forceinline__ uint32_t smem_u32(const void* p) {
    uint32_t a;
    asm("{ .reg .u64 t; cvta.to.shared.u64 t, %1; cvt.u32.u64 %0, t; }"
        : "=r"(a) : "l"(p));
    return a;
}

__device__ __forceinline__ void ldsm_x4(uint32_t& r0, uint32_t& r1, uint32_t& r2,
                                        uint32_t& r3, uint32_t addr) {
    asm volatile("ldmatrix.sync.aligned.m8n8.x4.shared.b16 {%0,%1,%2,%3}, [%4];"
                 : "=r"(r0), "=r"(r1), "=r"(r2), "=r"(r3) : "r"(addr));
}

__device__ __forceinline__ void mma16816(float* d, const uint32_t* a, const uint32_t* b) {
    asm volatile(
        "mma.sync.aligned.m16n8k16.row.col.f32.f16.f16.f32 "
        "{%0,%1,%2,%3}, {%4,%5,%6,%7}, {%8,%9}, {%0,%1,%2,%3};"
        : "+f"(d[0]), "+f"(d[1]), "+f"(d[2]), "+f"(d[3])
        : "r"(a[0]), "r"(a[1]), "r"(a[2]), "r"(a[3]), "r"(b[0]), "r"(b[1]));
}

__device__ __forceinline__ void cp16(uint32_t dst, const void* src) {
    asm volatile("cp.async.cg.shared.global [%0], [%1], 16;" :: "r"(dst), "l"(src));
}

__device__ __forceinline__ void pack_f16(const float* a, uint32_t* hv) {
    #pragma unroll
    for (int u = 0; u < 4; u++) {
        __half h0 = __float2half_rn(a[2 * u]);
        __half h1 = __float2half_rn(a[2 * u + 1]);
        hv[u] = ((uint32_t)__half_as_ushort(h1) << 16) | __half_as_ushort(h0);
    }
}

// ---------------------------------------------------------------------------
// Kernel 0: W^T fp16 image, pre-swizzled (coalesced reads).
// ---------------------------------------------------------------------------
__global__ void __launch_bounds__(256) prep_w_kernel(const float* __restrict__ W) {
    int e = blockIdx.x * 256 + threadIdx.x;   // 8192
    int lane = e & 31;
    int w = e >> 5;
    int n = (w & 7) * 32 + lane;
    int k0 = (w >> 3) * 8;
    float a[8];
    #pragma unroll
    for (int u = 0; u < 8; u++) a[u] = W[(size_t)(k0 + u) * CC + n];
    uint32_t hv[4];
    pack_f16(a, hv);
    uint32_t quad = (uint32_t)((k0 >> 3) & 3);
    uint32_t qs = quad ^ ((uint32_t)(n >> 1) & 3u);
    size_t off = (size_t)(k0 >> 5) * 16384 + (size_t)n * 64 + qs * 16;
    *(uint4*)(g_Bh + off) = make_uint4(hv[0], hv[1], hv[2], hv[3]);
}

// ---------------------------------------------------------------------------
// Kernel 1: conv. grid 256, 256 threads, ~21KB static SMEM -> high occupancy.
// min/bins/nb/conv -> A fp16 image (pre-swizzled) to global.
// ---------------------------------------------------------------------------
__global__ void __launch_bounds__(256) conv_kernel(
    const float* __restrict__ x, const float* __restrict__ eta,
    const float* __restrict__ phi, const float* __restrict__ ck,
    const float* __restrict__ cb)
{
    __shared__ float shK[9 * CC];
    __shared__ float shB[CC];
    __shared__ int sge[NN];
    __shared__ int sgp[NN];
    __shared__ int scnt[NN];
    __shared__ unsigned short nb[NN][32];
    __shared__ float wmin[8];
    __shared__ float mins[2];

    int b = blockIdx.x;
    int t = threadIdx.x;
    int lane = t & 31;
    int w = t >> 5;

    const float* xb = x + (size_t)b * NN * CC;

    // ---- per-batch min ----
    float ve = (t < NN) ? eta[b * NN + t] : 1e30f;
    float vp = (t < NN) ? phi[b * NN + t] : 1e30f;
    #pragma unroll
    for (int o = 16; o > 0; o >>= 1) {
        ve = fminf(ve, __shfl_xor_sync(0xffffffffu, ve, o));
        vp = fminf(vp, __shfl_xor_sync(0xffffffffu, vp, o));
    }
    if (lane == 0 && w < 4) { wmin[w] = ve; wmin[4 + w] = vp; }
    __syncthreads();
    if (t == 0) {
        mins[0] = fminf(fminf(wmin[0], wmin[1]), fminf(wmin[2], wmin[3]));
        mins[1] = fminf(fminf(wmin[4], wmin[5]), fminf(wmin[6], wmin[7]));
    }
    __syncthreads();
    if (t < NN) {
        sge[t] = (int)((eta[b * NN + t] - mins[0]) / 0.05f);
        sgp[t] = (int)((phi[b * NN + t] - mins[1]) / 0.05f);
    }
    __syncthreads();

    // ---- nb build (t<128, cap 32) | staging (t>=128) ----
    if (t < NN) {
        int gi = sge[t], pi = sgp[t];
        int cnt = 0;
        for (int j = 0; j < NN; j++) {
            unsigned dg = (unsigned)(sge[j] - gi + 1);
            unsigned dp = (unsigned)(sgp[j] - pi + 1);
            if (dg <= 2u && dp <= 2u && cnt < 32)
                nb[t][cnt++] = (unsigned short)(j | ((dg * 3 + dp) << 8));
        }
        scnt[t] = cnt;
    } else {
        int u = t - 128;
        for (int i = u; i < 9 * CC; i += 128) shK[i] = ck[i];
        for (int i = u; i < CC; i += 128) shB[i] = cb[i];
    }
    __syncthreads();

    // ---- conv -> A image (fp16, quad-XOR swizzle) ----
    {
        int c0 = lane * 8;
        unsigned char* achunk = g_Ah + (size_t)b * 65536 + (size_t)(lane >> 2) * 8192;
        uint32_t q = (uint32_t)(lane & 3);

        #pragma unroll
        for (int s = 0; s < 16; s++) {
            int i = w * 16 + s;
            float acc[8];
            #pragma unroll
            for (int u = 0; u < 8; u++) acc[u] = shB[c0 + u];

            int cnt = scnt[i];
            for (int e = 0; e < cnt; e++) {
                int pk = nb[i][e];
                int j = pk & 0xFF;
                int kk = pk >> 8;
                const float4* xp = (const float4*)(xb + (size_t)j * CC + c0);
                float4 a0 = xp[0];
                float4 a1 = xp[1];
                const float4* kp = (const float4*)(shK + kk * CC + c0);
                float4 k0 = kp[0];
                float4 k1 = kp[1];
                acc[0] += k0.x * a0.x; acc[1] += k0.y * a0.y;
                acc[2] += k0.z * a0.z; acc[3] += k0.w * a0.w;
                acc[4] += k1.x * a1.x; acc[5] += k1.y * a1.y;
                acc[6] += k1.z * a1.z; acc[7] += k1.w * a1.w;
            }

            uint32_t hv[4];
            pack_f16(acc, hv);
            uint32_t qs = q ^ ((uint32_t)(i >> 1) & 3u);
            *(uint4*)(achunk + i * 64 + qs * 16) = make_uint4(hv[0], hv[1], hv[2], hv[3]);
        }
    }
}

// ---------------------------------------------------------------------------
// Kernel 2: GEMM + LN. grid 256, 512 threads, 204KB SMEM.
// Flat cp.async stage of A+B, one rendezvous, barrier-free GEMM, LN epilogue.
// ---------------------------------------------------------------------------
#define SA      0               // 65536
#define SB      65536           // 131072
#define SPAR    196608          // db, gamma, beta (3 x 1024)
#define SRED    199680          // redS 4096 + redQ 4096
#define SMI     207872          // float2[128]
#define SMEMT   208896

__global__ void __launch_bounds__(512, 1) gemm_ln_kernel(
    const float* __restrict__ x, const float* __restrict__ db,
    const float* __restrict__ gamma, const float* __restrict__ beta,
    float* __restrict__ out)
{
    extern __shared__ char smem[];
    uint32_t sb = smem_u32(smem);
    int b = blockIdx.x;
    int t = threadIdx.x;
    int lane = t & 31;
    int w = t >> 5;

    // ---- stage A (64KB) + B (128KB), flat coalesced ----
    const unsigned char* gA = g_Ah + (size_t)b * 65536;
    #pragma unroll
    for (int p = 0; p < 8; p++) {
        int idx = t + p * 512;                // 4096 uint4
        cp16(sb + SA + idx * 16, gA + (size_t)idx * 16);
    }
    #pragma unroll
    for (int p = 0; p < 16; p++) {
        int idx = t + p * 512;                // 8192 uint4
        cp16(sb + SB + idx * 16, g_Bh + (size_t)idx * 16);
    }
    asm volatile("cp.async.commit_group;" ::: "memory");

    if (t < 256) {
        ((float*)(smem + SPAR))[t]        = db[t];
        ((float*)(smem + SPAR + 1024))[t] = gamma[t];
        ((float*)(smem + SPAR + 2048))[t] = beta[t];
    }

    asm volatile("cp.async.wait_group 0;" ::: "memory");
    __syncthreads();

    // ---- GEMM: M=128 N=256 K=256, 16 warps, warp tile 64x32, no barriers ----
    int mw = w & 1;
    int nw = w >> 1;

    float acc[4][4][4];
    #pragma unroll
    for (int i = 0; i < 4; i++)
        #pragma unroll
        for (int j = 0; j < 4; j++)
            #pragma unroll
            for (int d = 0; d < 4; d++) acc[i][j][d] = 0.f;

    int aRow0 = mw * 64 + (lane & 7) + ((lane >> 3) & 1) * 8;
    uint32_t qk = (uint32_t)(lane >> 4);

    int bRow = (lane & 7) + ((lane >= 16) ? 8 : 0);
    uint32_t qb = (uint32_t)((lane >> 3) & 1);
    int bR[2];
    uint32_t bSw[2];
    #pragma unroll
    for (int np = 0; np < 2; np++) {
        bR[np] = nw * 32 + bRow + np * 16;
        bSw[np] = ((uint32_t)(bR[np] >> 1) & 3u);
    }

    for (int kc = 0; kc < 8; kc++) {
        uint32_t ca = sb + SA + kc * 8192;
        uint32_t cbase = sb + SB + kc * 16384;

        #pragma unroll
        for (int ks = 0; ks < 2; ks++) {
            uint32_t av[4][4], bf[4][2];
            #pragma unroll
            for (int mt = 0; mt < 4; mt++) {
                int row = aRow0 + mt * 16;
                uint32_t qs = (((uint32_t)(ks * 2) + qk) ^ ((uint32_t)(row >> 1) & 3u)) * 16;
                ldsm_x4(av[mt][0], av[mt][1], av[mt][2], av[mt][3],
                        ca + row * 64 + qs);
            }
            #pragma unroll
            for (int np = 0; np < 2; np++) {
                uint32_t qs = (((uint32_t)(ks * 2) + qb) ^ bSw[np]) * 16;
                uint32_t r0, r1, r2, r3;
                ldsm_x4(r0, r1, r2, r3, cbase + bR[np] * 64 + qs);
                bf[2 * np][0] = r0; bf[2 * np][1] = r1;
                bf[2 * np + 1][0] = r2; bf[2 * np + 1][1] = r3;
            }
            #pragma unroll
            for (int mt = 0; mt < 4; mt++)
                #pragma unroll
                for (int nt = 0; nt < 4; nt++)
                    mma16816(acc[mt][nt], av[mt], bf[nt]);
        }
    }

    // ---- epilogue: bias + LN + residual ----
    const float* s_db = (const float*)(smem + SPAR);
    const float* s_g  = (const float*)(smem + SPAR + 1024);
    const float* s_bt = (const float*)(smem + SPAR + 2048);
    float* redS = (float*)(smem + SRED);
    float* redQ = (float*)(smem + SRED + 4096);
    float2* smi = (float2*)(smem + SMI);

    int qr = lane >> 2, qc = lane & 3;
    int MW = mw * 64, NW = nw * 32;

    float S[4][2], Q[4][2];
    #pragma unroll
    for (int mt = 0; mt < 4; mt++) {
        S[mt][0] = S[mt][1] = 0.f;
        Q[mt][0] = Q[mt][1] = 0.f;
    }
    #pragma unroll
    for (int mt = 0; mt < 4; mt++)
        #pragma unroll
        for (int nt = 0; nt < 4; nt++)
            #pragma unroll
            for (int d = 0; d < 4; d++) {
                int col = NW + nt * 8 + qc * 2 + (d & 1);
                float v = acc[mt][nt][d] + s_db[col];
                acc[mt][nt][d] = v;
                S[mt][d >> 1] += v;
                Q[mt][d >> 1] += v * v;
            }
    #pragma unroll
    for (int mt = 0; mt < 4; mt++)
        #pragma unroll
        for (int h = 0; h < 2; h++) {
            #pragma unroll
            for (int off = 1; off <= 2; off <<= 1) {
                S[mt][h] += __shfl_xor_sync(0xffffffffu, S[mt][h], off);
                Q[mt][h] += __shfl_xor_sync(0xffffffffu, Q[mt][h], off);
            }
        }
    if (qc == 0) {
        #pragma unroll
        for (int mt = 0; mt < 4; mt++)
            #pragma unroll
            for (int h = 0; h < 2; h++) {
                int row = MW + mt * 16 + qr + h * 8;
                redS[row * 8 + nw] = S[mt][h];
                redQ[row * 8 + nw] = Q[mt][h];
            }
    }
    __syncthreads();

    if (t < 128) {
        float s = 0.f, q = 0.f;
        #pragma unroll
        for (int k = 0; k < 8; k++) {
            s += redS[t * 8 + k];
            q += redQ[t * 8 + k];
        }
        float mean = s * (1.0f / 256.0f);
        float var = fmaf(-mean, mean, q * (1.0f / 256.0f));
        smi[t] = make_float2(mean, rsqrtf(var + 1e-6f));
    }
    __syncthreads();

    #pragma unroll
    for (int mt = 0; mt < 4; mt++)
        #pragma unroll
        for (int h = 0; h < 2; h++) {
            int row = MW + mt * 16 + qr + h * 8;
            float2 mv = smi[row];
            size_t rb = ((size_t)b * NN + row) * CC;
            #pragma unroll
            for (int nt = 0; nt < 4; nt++) {
                int col = NW + nt * 8 + qc * 2;
                float2 xv = *(const float2*)(x + rb + col);
                float v0 = (acc[mt][nt][h * 2]     - mv.x) * mv.y * s_g[col]     + s_bt[col]     + xv.x;
                float v1 = (acc[mt][nt][h * 2 + 1] - mv.x) * mv.y * s_g[col + 1] + s_bt[col + 1] + xv.y;
                *(float2*)(out + rb + col) = make_float2(v0, v1);
            }
        }
}

extern "C" void kernel_launch(void* const* d_in, const int* in_sizes, int n_in,
                              void* d_out, int out_size) {
    const float* x   = (const float*)d_in[0];
    const float* eta = (const float*)d_in[1];
    const float* phi = (const float*)d_in[2];
    const float* ck  = (const float*)d_in[3];
    const float* cb  = (const float*)d_in[4];
    const float* dw  = (const float*)d_in[5];
    const float* db  = (const float*)d_in[6];
    const float* gm  = (const float*)d_in[7];
    const float* bt  = (const float*)d_in[8];
    float* out = (float*)d_out;

    cudaFuncSetAttribute(gemm_ln_kernel,
                         cudaFuncAttributeMaxDynamicSharedMemorySize, SMEMT);

    prep_w_kernel<<<32, 256>>>(dw);
    conv_kernel<<<BB, 256>>>(x, eta, phi, ck, cb);
    gemm_ln_kernel<<<BB, 512, SMEMT>>>(x, db, gm, bt, out);
}

// round 13
// speedup vs baseline: 1.0666x; 1.0666x over previous
#include <cuda_runtime.h>
#include <cuda_fp16.h>
#include <cstdint>

#define BB 256
#define NN 128
#define CC 256
#define GRID2 148

// B = W^T fp16 image, pre-swizzled quad-XOR: [8 chunks 16KB][256 rows 64B].
__device__ __align__(16) unsigned char g_Bh[131072];
// A fp16 images, same layout per batch: [8 chunks 8KB][128 rows 64B].
__device__ __align__(16) unsigned char g_Ah[(size_t)BB * 65536];

__device__ __forceinline__ uint32_t smem_u32(const void* p) {
    uint32_t a;
    asm("{ .reg .u64 t; cvta.to.shared.u64 t, %1; cvt.u32.u64 %0, t; }"
        : "=r"(a) : "l"(p));
    return a;
}

__device__ __forceinline__ void ldsm_x4(uint32_t& r0, uint32_t& r1, uint32_t& r2,
                                        uint32_t& r3, uint32_t addr) {
    asm volatile("ldmatrix.sync.aligned.m8n8.x4.shared.b16 {%0,%1,%2,%3}, [%4];"
                 : "=r"(r0), "=r"(r1), "=r"(r2), "=r"(r3) : "r"(addr));
}

__device__ __forceinline__ void mma16816(float* d, const uint32_t* a, const uint32_t* b) {
    asm volatile(
        "mma.sync.aligned.m16n8k16.row.col.f32.f16.f16.f32 "
        "{%0,%1,%2,%3}, {%4,%5,%6,%7}, {%8,%9}, {%0,%1,%2,%3};"
        : "+f"(d[0]), "+f"(d[1]), "+f"(d[2]), "+f"(d[3])
        : "r"(a[0]), "r"(a[1]), "r"(a[2]), "r"(a[3]), "r"(b[0]), "r"(b[1]));
}

__device__ __forceinline__ void cp16(uint32_t dst, const void* src) {
    asm volatile("cp.async.cg.shared.global [%0], [%1], 16;" :: "r"(dst), "l"(src));
}

__device__ __forceinline__ void pack_f16(const float* a, uint32_t* hv) {
    #pragma unroll
    for (int u = 0; u < 4; u++) {
        __half h0 = __float2half_rn(a[2 * u]);
        __half h1 = __float2half_rn(a[2 * u + 1]);
        hv[u] = ((uint32_t)__half_as_ushort(h1) << 16) | __half_as_ushort(h0);
    }
}

// ---------------------------------------------------------------------------
// Kernel 1: conv (+ folded W prep in CTAs b<32). grid 256, 256 threads.
// ---------------------------------------------------------------------------
__global__ void __launch_bounds__(256) conv_kernel(
    const float* __restrict__ x, const float* __restrict__ eta,
    const float* __restrict__ phi, const float* __restrict__ ck,
    const float* __restrict__ cb, const float* __restrict__ W)
{
    __shared__ float shK[9 * CC];
    __shared__ float shB[CC];
    __shared__ int sge[NN];
    __shared__ int sgp[NN];
    __shared__ int scnt[NN];
    __shared__ unsigned short nb[NN][32];
    __shared__ float wmin[8];
    __shared__ float mins[2];

    int b = blockIdx.x;
    int t = threadIdx.x;
    int lane = t & 31;
    int w = t >> 5;

    // ---- folded W prep: CTAs 0..31 each convert 256 quads of W^T ----
    if (b < 32) {
        int e = b * 256 + t;
        int n = ((e >> 5) & 7) * 32 + (e & 31);
        int k0 = (e >> 8) * 8;
        float a[8];
        #pragma unroll
        for (int u = 0; u < 8; u++) a[u] = W[(size_t)(k0 + u) * CC + n];
        uint32_t hv[4];
        pack_f16(a, hv);
        uint32_t quad = (uint32_t)((k0 >> 3) & 3);
        uint32_t qs = quad ^ ((uint32_t)(n >> 1) & 3u);
        size_t off = (size_t)(k0 >> 5) * 16384 + (size_t)n * 64 + qs * 16;
        *(uint4*)(g_Bh + off) = make_uint4(hv[0], hv[1], hv[2], hv[3]);
    }

    const float* xb = x + (size_t)b * NN * CC;

    // ---- per-batch min ----
    float ve = (t < NN) ? eta[b * NN + t] : 1e30f;
    float vp = (t < NN) ? phi[b * NN + t] : 1e30f;
    #pragma unroll
    for (int o = 16; o > 0; o >>= 1) {
        ve = fminf(ve, __shfl_xor_sync(0xffffffffu, ve, o));
        vp = fminf(vp, __shfl_xor_sync(0xffffffffu, vp, o));
    }
    if (lane == 0 && w < 4) { wmin[w] = ve; wmin[4 + w] = vp; }
    __syncthreads();
    if (t == 0) {
        mins[0] = fminf(fminf(wmin[0], wmin[1]), fminf(wmin[2], wmin[3]));
        mins[1] = fminf(fminf(wmin[4], wmin[5]), fminf(wmin[6], wmin[7]));
    }
    __syncthreads();
    if (t < NN) {
        sge[t] = (int)((eta[b * NN + t] - mins[0]) / 0.05f);
        sgp[t] = (int)((phi[b * NN + t] - mins[1]) / 0.05f);
    }
    __syncthreads();

    // ---- nb build (t<128, cap 32) | staging (t>=128) ----
    if (t < NN) {
        int gi = sge[t], pi = sgp[t];
        int cnt = 0;
        for (int j = 0; j < NN; j++) {
            unsigned dg = (unsigned)(sge[j] - gi + 1);
            unsigned dp = (unsigned)(sgp[j] - pi + 1);
            if (dg <= 2u && dp <= 2u && cnt < 32)
                nb[t][cnt++] = (unsigned short)(j | ((dg * 3 + dp) << 8));
        }
        scnt[t] = cnt;
    } else {
        int u = t - 128;
        for (int i = u; i < 9 * CC; i += 128) shK[i] = ck[i];
        for (int i = u; i < CC; i += 128) shB[i] = cb[i];
    }
    __syncthreads();

    // ---- conv -> A image (fp16, quad-XOR swizzle) ----
    {
        int c0 = lane * 8;
        unsigned char* achunk = g_Ah + (size_t)b * 65536 + (size_t)(lane >> 2) * 8192;
        uint32_t q = (uint32_t)(lane & 3);

        #pragma unroll
        for (int s = 0; s < 16; s++) {
            int i = w * 16 + s;
            float acc[8];
            #pragma unroll
            for (int u = 0; u < 8; u++) acc[u] = shB[c0 + u];

            int cnt = scnt[i];
            for (int e = 0; e < cnt; e++) {
                int pk = nb[i][e];
                int j = pk & 0xFF;
                int kk = pk >> 8;
                const float4* xp = (const float4*)(xb + (size_t)j * CC + c0);
                float4 a0 = xp[0];
                float4 a1 = xp[1];
                const float4* kp = (const float4*)(shK + kk * CC + c0);
                float4 k0 = kp[0];
                float4 k1 = kp[1];
                acc[0] += k0.x * a0.x; acc[1] += k0.y * a0.y;
                acc[2] += k0.z * a0.z; acc[3] += k0.w * a0.w;
                acc[4] += k1.x * a1.x; acc[5] += k1.y * a1.y;
                acc[6] += k1.z * a1.z; acc[7] += k1.w * a1.w;
            }

            uint32_t hv[4];
            pack_f16(acc, hv);
            uint32_t qs = q ^ ((uint32_t)(i >> 1) & 3u);
            *(uint4*)(achunk + i * 64 + qs * 16) = make_uint4(hv[0], hv[1], hv[2], hv[3]);
        }
    }
}

// ---------------------------------------------------------------------------
// Kernel 2: persistent GEMM + LN. grid 148, 512 threads, ~209KB SMEM.
// B staged ONCE per CTA; A re-staged per batch, prefetch hidden under epilogue.
// ---------------------------------------------------------------------------
#define SA      131072          // 65536
#define SB      0               // 131072
#define SPAR    196608          // db, gamma, beta (3 x 1024)
#define SRED    199680          // redS 4096 + redQ 4096
#define SMI     207872          // float2[128]
#define SMEMT   208896

__global__ void __launch_bounds__(512, 1) gemm_ln_kernel(
    const float* __restrict__ x, const float* __restrict__ db,
    const float* __restrict__ gamma, const float* __restrict__ beta,
    float* __restrict__ out)
{
    extern __shared__ char smem[];
    uint32_t sb = smem_u32(smem);
    int t = threadIdx.x;
    int lane = t & 31;
    int w = t >> 5;

    // ---- stage B (128KB, once) + A(b0) ----
    #pragma unroll
    for (int p = 0; p < 16; p++) {
        int idx = t + p * 512;
        cp16(sb + SB + idx * 16, g_Bh + (size_t)idx * 16);
    }
    {
        const unsigned char* gA = g_Ah + (size_t)blockIdx.x * 65536;
        #pragma unroll
        for (int p = 0; p < 8; p++) {
            int idx = t + p * 512;
            cp16(sb + SA + idx * 16, gA + (size_t)idx * 16);
        }
    }
    asm volatile("cp.async.commit_group;" ::: "memory");

    if (t < 256) {
        ((float*)(smem + SPAR))[t]        = db[t];
        ((float*)(smem + SPAR + 1024))[t] = gamma[t];
        ((float*)(smem + SPAR + 2048))[t] = beta[t];
    }

    // lane-constant mappings
    int mw = w & 1;
    int nw = w >> 1;
    int aRow0 = mw * 64 + (lane & 7) + ((lane >> 3) & 1) * 8;
    uint32_t qk = (uint32_t)(lane >> 4);
    int bRow = (lane & 7) + ((lane >= 16) ? 8 : 0);
    uint32_t qb = (uint32_t)((lane >> 3) & 1);
    int bR[2];
    uint32_t bSw[2];
    #pragma unroll
    for (int np = 0; np < 2; np++) {
        bR[np] = nw * 32 + bRow + np * 16;
        bSw[np] = ((uint32_t)(bR[np] >> 1) & 3u);
    }

    const float* s_db = (const float*)(smem + SPAR);
    const float* s_g  = (const float*)(smem + SPAR + 1024);
    const float* s_bt = (const float*)(smem + SPAR + 2048);
    float* redS = (float*)(smem + SRED);
    float* redQ = (float*)(smem + SRED + 4096);
    float2* smi = (float2*)(smem + SMI);
    int qr = lane >> 2, qc = lane & 3;
    int MW = mw * 64, NW = nw * 32;

    for (int bi = 0; bi < 2; bi++) {
        int b = blockIdx.x + bi * GRID2;
        if (b >= BB) break;

        asm volatile("cp.async.wait_group 0;" ::: "memory");
        __syncthreads();

        // ---- GEMM: barrier-free 8-chunk loop ----
        float acc[4][4][4];
        #pragma unroll
        for (int i = 0; i < 4; i++)
            #pragma unroll
            for (int j = 0; j < 4; j++)
                #pragma unroll
                for (int d = 0; d < 4; d++) acc[i][j][d] = 0.f;

        for (int kc = 0; kc < 8; kc++) {
            uint32_t ca = sb + SA + kc * 8192;
            uint32_t cbase = sb + SB + kc * 16384;
            #pragma unroll
            for (int ks = 0; ks < 2; ks++) {
                uint32_t av[4][4], bf[4][2];
                #pragma unroll
                for (int mt = 0; mt < 4; mt++) {
                    int row = aRow0 + mt * 16;
                    uint32_t qs = (((uint32_t)(ks * 2) + qk) ^ ((uint32_t)(row >> 1) & 3u)) * 16;
                    ldsm_x4(av[mt][0], av[mt][1], av[mt][2], av[mt][3],
                            ca + row * 64 + qs);
                }
                #pragma unroll
                for (int np = 0; np < 2; np++) {
                    uint32_t qs = (((uint32_t)(ks * 2) + qb) ^ bSw[np]) * 16;
                    uint32_t r0, r1, r2, r3;
                    ldsm_x4(r0, r1, r2, r3, cbase + bR[np] * 64 + qs);
                    bf[2 * np][0] = r0; bf[2 * np][1] = r1;
                    bf[2 * np + 1][0] = r2; bf[2 * np + 1][1] = r3;
                }
                #pragma unroll
                for (int mt = 0; mt < 4; mt++)
                    #pragma unroll
                    for (int nt = 0; nt < 4; nt++)
                        mma16816(acc[mt][nt], av[mt], bf[nt]);
            }
        }

        __syncthreads();    // all warps done reading A(b)

        // ---- prefetch A(next batch) under the epilogue ----
        if (bi == 0 && blockIdx.x + GRID2 < BB) {
            const unsigned char* gA = g_Ah + (size_t)(blockIdx.x + GRID2) * 65536;
            #pragma unroll
            for (int p = 0; p < 8; p++) {
                int idx = t + p * 512;
                cp16(sb + SA + idx * 16, gA + (size_t)idx * 16);
            }
            asm volatile("cp.async.commit_group;" ::: "memory");
        }

        // ---- epilogue: bias + LN + residual ----
        float S[4][2], Q[4][2];
        #pragma unroll
        for (int mt = 0; mt < 4; mt++) {
            S[mt][0] = S[mt][1] = 0.f;
            Q[mt][0] = Q[mt][1] = 0.f;
        }
        #pragma unroll
        for (int mt = 0; mt < 4; mt++)
            #pragma unroll
            for (int nt = 0; nt < 4; nt++)
                #pragma unroll
                for (int d = 0; d < 4; d++) {
                    int col = NW + nt * 8 + qc * 2 + (d & 1);
                    float v = acc[mt][nt][d] + s_db[col];
                    acc[mt][nt][d] = v;
                    S[mt][d >> 1] += v;
                    Q[mt][d >> 1] += v * v;
                }
        #pragma unroll
        for (int mt = 0; mt < 4; mt++)
            #pragma unroll
            for (int h = 0; h < 2; h++) {
                #pragma unroll
                for (int off = 1; off <= 2; off <<= 1) {
                    S[mt][h] += __shfl_xor_sync(0xffffffffu, S[mt][h], off);
                    Q[mt][h] += __shfl_xor_sync(0xffffffffu, Q[mt][h], off);
                }
            }
        if (qc == 0) {
            #pragma unroll
            for (int mt = 0; mt < 4; mt++)
                #pragma unroll
                for (int h = 0; h < 2; h++) {
                    int row = MW + mt * 16 + qr + h * 8;
                    redS[row * 8 + nw] = S[mt][h];
                    redQ[row * 8 + nw] = Q[mt][h];
                }
        }
        __syncthreads();

        if (t < 128) {
            float s = 0.f, q = 0.f;
            #pragma unroll
            for (int k = 0; k < 8; k++) {
                s += redS[t * 8 + k];
                q += redQ[t * 8 + k];
            }
            float mean = s * (1.0f / 256.0f);
            float var = fmaf(-mean, mean, q * (1.0f / 256.0f));
            smi[t] = make_float2(mean, rsqrtf(var + 1e-6f));
        }
        __syncthreads();

        #pragma unroll
        for (int mt = 0; mt < 4; mt++)
            #pragma unroll
            for (int h = 0; h < 2; h++) {
                int row = MW + mt * 16 + qr + h * 8;
                float2 mv = smi[row];
                size_t rb = ((size_t)b * NN + row) * CC;
                #pragma unroll
                for (int nt = 0; nt < 4; nt++) {
                    int col = NW + nt * 8 + qc * 2;
                    float2 xv = *(const float2*)(x + rb + col);
                    float v0 = (acc[mt][nt][h * 2]     - mv.x) * mv.y * s_g[col]     + s_bt[col]     + xv.x;
                    float v1 = (acc[mt][nt][h * 2 + 1] - mv.x) * mv.y * s_g[col + 1] + s_bt[col + 1] + xv.y;
                    *(float2*)(out + rb + col) = make_float2(v0, v1);
                }
            }
        __syncthreads();   // epilogue reads of redS/smi done before next batch writes
    }
}

extern "C" void kernel_launch(void* const* d_in, const int* in_sizes, int n_in,
                              void* d_out, int out_size) {
    const float* x   = (const float*)d_in[0];
    const float* eta = (const float*)d_in[1];
    const float* phi = (const float*)d_in[2];
    const float* ck  = (const float*)d_in[3];
    const float* cb  = (const float*)d_in[4];
    const float* dw  = (const float*)d_in[5];
    const float* db  = (const float*)d_in[6];
    const float* gm  = (const float*)d_in[7];
    const float* bt  = (const float*)d_in[8];
    float* out = (float*)d_out;

    cudaFuncSetAttribute(gemm_ln_kernel,
                         cudaFuncAttributeMaxDynamicSharedMemorySize, SMEMT);

    conv_kernel<<<BB, 256>>>(x, eta, phi, ck, cb, dw);
    gemm_ln_kernel<<<GRID2, 512, SMEMT>>>(x, db, gm, bt, out);
}